// round 5
// baseline (speedup 1.0000x reference)
#include <cuda_runtime.h>
#include <cstdint>

#define N_NODES 100000
#define N_EDGES 1600000
#define NB 296          // 2 blocks per SM x 148 SMs -> guaranteed co-resident
#define NT 256
#define NCHUNK 196      // 196*512 >= N_NODES (scan chunks)

// ---------------- scratch (device globals; no allocation allowed) ----------
__device__ float g_y[N_NODES * 32];     // x @ W1_l
__device__ float g_z[N_NODES * 32];     // x @ W1_r
__device__ float g_h1[N_NODES * 32];
__device__ int2  g_edge[N_EDGES];       // packed (src, dst)
__device__ int   g_csr[N_EDGES];        // src ids grouped by dst
__device__ int   g_off[N_NODES + 1];    // counts -> exclusive offsets
__device__ int   g_part[N_NODES + 512]; // scan partials
__device__ int   g_cur[N_NODES];        // bucket cursors
__device__ int   g_bsum[256];
__device__ int   g_is64;
__device__ unsigned g_arrive;
__device__ unsigned g_release;

// ---------------- JAX threefry2x32 (partitionable scheme) ------------------
struct TF2 { uint32_t a, b; };

__host__ __device__ constexpr uint32_t rotl32(uint32_t v, int r) {
    return (v << r) | (v >> (32 - r));
}

__host__ __device__ constexpr TF2 threefry(uint32_t k0, uint32_t k1,
                                           uint32_t x0, uint32_t x1) {
    const uint32_t ks0 = k0, ks1 = k1, ks2 = k0 ^ k1 ^ 0x1BD11BDAu;
    const int ra[4] = {13, 15, 26, 6};
    const int rb[4] = {17, 29, 16, 24};
    x0 += ks0; x1 += ks1;
#pragma unroll
    for (int i = 0; i < 4; i++) { x0 += x1; x1 = rotl32(x1, ra[i]); x1 ^= x0; }
    x0 += ks1; x1 += ks2 + 1u;
#pragma unroll
    for (int i = 0; i < 4; i++) { x0 += x1; x1 = rotl32(x1, rb[i]); x1 ^= x0; }
    x0 += ks2; x1 += ks0 + 2u;
#pragma unroll
    for (int i = 0; i < 4; i++) { x0 += x1; x1 = rotl32(x1, ra[i]); x1 ^= x0; }
    x0 += ks0; x1 += ks1 + 3u;
#pragma unroll
    for (int i = 0; i < 4; i++) { x0 += x1; x1 = rotl32(x1, rb[i]); x1 ^= x0; }
    x0 += ks1; x1 += ks2 + 4u;
#pragma unroll
    for (int i = 0; i < 4; i++) { x0 += x1; x1 = rotl32(x1, ra[i]); x1 ^= x0; }
    x0 += ks2; x1 += ks0 + 5u;
    return {x0, x1};
}

constexpr TF2 DK0 = threefry(0u, 42u, 0u, 0u);
constexpr TF2 DK1 = threefry(0u, 42u, 0u, 1u);

template <uint32_t K0, uint32_t K1>
__device__ __forceinline__ bool drop_bit(uint32_t j) {
    TF2 r = threefry(K0, K1, 0u, j);
    return ((r.a ^ r.b) >> 31) != 0;   // MSB set -> u >= 0.5 -> dropped
}

// ---------------- reset kernel ---------------------------------------------
__global__ void k_reset(const uint32_t* __restrict__ ei) {
    int i = blockIdx.x * NT + threadIdx.x;
    if (i <= N_NODES) g_off[i] = 0;
    if (i == 0) {
        g_arrive = 0u;
        g_release = 0u;
        int is64 = 1;
        for (int k = 0; k < 64; k++)
            if (ei[2 * k + 1] != 0u) { is64 = 0; break; }
        g_is64 = is64;
    }
}

// ---------------- persistent fused kernel -----------------------------------
__global__ void __launch_bounds__(NT, 2)
k_main(const float* __restrict__ x, const uint32_t* __restrict__ ei,
       const float* __restrict__ W1l, const float* __restrict__ b1,
       const float* __restrict__ W1r, const float* __restrict__ W2l,
       const float* __restrict__ b2,  const float* __restrict__ W2r,
       float* __restrict__ out) {
    __shared__ float swl[2048], swr[2048];
    __shared__ float rows[8][64];
    __shared__ int   sint[256];

    const int tid = threadIdx.x;
    const int bid = blockIdx.x;
    const int w = tid >> 5, lane = tid & 31;
    unsigned target = 0;

    auto GBAR = [&]() {
        __syncthreads();
        __threadfence();
        target += 1;
        if (tid == 0) {
            unsigned a = atomicAdd(&g_arrive, 1u) + 1u;
            if (a == target * NB) {
                *((volatile unsigned*)&g_release) = target;
            } else {
                while (*((volatile unsigned*)&g_release) < target) __nanosleep(64);
            }
        }
        __syncthreads();
    };

    // ---- P0a: y = x @ W1_l, z = x @ W1_r ----
    for (int i = tid; i < 2048; i += NT) { swl[i] = W1l[i]; swr[i] = W1r[i]; }
    __syncthreads();
    for (int node = bid * 8 + w; node < N_NODES; node += NB * 8) {
        rows[w][lane]      = x[node * 64 + lane];
        rows[w][32 + lane] = x[node * 64 + 32 + lane];
        __syncwarp();
        float accl = 0.f, accr = 0.f;
#pragma unroll
        for (int k = 0; k < 64; k++) {
            float xv = rows[w][k];
            accl = fmaf(xv, swl[k * 32 + lane], accl);
            accr = fmaf(xv, swr[k * 32 + lane], accr);
        }
        g_y[node * 32 + lane] = accl;
        g_z[node * 32 + lane] = accr;
        __syncwarp();
    }
    // ---- P0b: pack edges + dst histogram ----
    {
        int is64 = g_is64;
        for (int e = bid * NT + tid; e < N_EDGES; e += NB * NT) {
            int s, d;
            if (is64) {
                uint2 sv = reinterpret_cast<const uint2*>(ei)[e];
                uint2 dv = reinterpret_cast<const uint2*>(ei)[N_EDGES + e];
                s = (int)sv.x; d = (int)dv.x;
            } else {
                s = (int)ei[e];
                d = (int)ei[N_EDGES + e];
            }
            g_edge[e] = make_int2(s, d);
            atomicAdd(&g_off[d], 1);
        }
    }
    GBAR();   // 1

    // ---- P1a: per-chunk scan (512 counts per chunk, 2 per thread) ----
    if (bid < NCHUNK) {
        int base = bid * 512;
        int i0 = base + tid * 2;
        int v0 = (i0     < N_NODES) ? __ldcg(&g_off[i0])     : 0;
        int v1 = (i0 + 1 < N_NODES) ? __ldcg(&g_off[i0 + 1]) : 0;
        int s2 = v0 + v1;
        sint[tid] = s2;
        __syncthreads();
        for (int o = 1; o < 256; o <<= 1) {
            int t = (tid >= o) ? sint[tid - o] : 0;
            __syncthreads();
            sint[tid] += t;
            __syncthreads();
        }
        int ex = sint[tid] - s2;
        if (i0     < N_NODES) g_part[i0]     = ex;
        if (i0 + 1 < N_NODES) g_part[i0 + 1] = ex + v0;
        if (tid == 255) g_bsum[bid] = sint[255];
    }
    GBAR();   // 2

    // ---- P1b: scan the 196 chunk totals (block 0) ----
    if (bid == 0) {
        int v = (tid < NCHUNK) ? __ldcg(&g_bsum[tid]) : 0;
        sint[tid] = v;
        __syncthreads();
        for (int o = 1; o < 256; o <<= 1) {
            int t = (tid >= o) ? sint[tid - o] : 0;
            __syncthreads();
            sint[tid] += t;
            __syncthreads();
        }
        if (tid < NCHUNK) g_bsum[tid] = sint[tid] - v;
    }
    GBAR();   // 3

    // ---- P1c: add chunk bases -> final offsets + cursors ----
    if (bid < NCHUNK) {
        int bb = __ldcg(&g_bsum[bid]);
        for (int idx = tid; idx < 512; idx += NT) {
            int i = bid * 512 + idx;
            if (i < N_NODES) {
                int o = g_part[i] + bb;
                g_off[i] = o;
                g_cur[i] = o;
            }
        }
    }
    if (bid == 0 && tid == 0) g_off[N_NODES] = N_EDGES;
    GBAR();   // 4

    // ---- P2: bucket scatter (CSR fill) ----
    for (int e = bid * NT + tid; e < N_EDGES; e += NB * NT) {
        int2 p = g_edge[e];
        int pos = atomicAdd(&g_cur[p.y], 1);
        g_csr[pos] = p.x;
    }
    GBAR();   // 5

    // ---- P3: layer-1 gather-mean + bias + z + lrelu + dropout ----
    {
        float bb1 = __ldg(&b1[lane]);
        for (int node = bid * 8 + w; node < N_NODES; node += NB * 8) {
            int beg = __ldcg(&g_off[node]);
            int end = __ldcg(&g_off[node + 1]);
            float acc = 0.f;
            int j = beg;
            for (; j + 4 <= end; j += 4) {
                int s0 = __ldg(g_csr + j),     s1 = __ldg(g_csr + j + 1);
                int s2 = __ldg(g_csr + j + 2), s3 = __ldg(g_csr + j + 3);
                float v0 = __ldg(g_y + s0 * 32 + lane);
                float v1 = __ldg(g_y + s1 * 32 + lane);
                float v2 = __ldg(g_y + s2 * 32 + lane);
                float v3 = __ldg(g_y + s3 * 32 + lane);
                acc += (v0 + v1) + (v2 + v3);
            }
            for (; j < end; j++)
                acc += __ldg(g_y + __ldg(g_csr + j) * 32 + lane);
            float inv = 1.0f / fmaxf((float)(end - beg), 1.0f);
            float v = fmaf(acc, inv, bb1 + g_z[node * 32 + lane]);
            v = v > 0.f ? v : 0.01f * v;
            uint32_t jj = (uint32_t)(node * 32 + lane);
            g_h1[jj] = drop_bit<DK0.a, DK0.b>(jj) ? 0.f : 2.0f * v;
        }
    }
    GBAR();   // 6

    // ---- P4: layer-2 gather-mean + GEMMs + dropout + l2norm ----
    for (int i = tid; i < 2048; i += NT) { swl[i] = W2l[i]; swr[i] = W2r[i]; }
    __syncthreads();
    {
        float bb0  = __ldg(&b2[lane]);
        float bb32 = __ldg(&b2[32 + lane]);
        for (int node = bid * 8 + w; node < N_NODES; node += NB * 8) {
            int beg = __ldcg(&g_off[node]);
            int end = __ldcg(&g_off[node + 1]);
            float acc = 0.f;
            int j = beg;
            for (; j + 4 <= end; j += 4) {
                int s0 = __ldg(g_csr + j),     s1 = __ldg(g_csr + j + 1);
                int s2 = __ldg(g_csr + j + 2), s3 = __ldg(g_csr + j + 3);
                float v0 = __ldg(g_h1 + s0 * 32 + lane);
                float v1 = __ldg(g_h1 + s1 * 32 + lane);
                float v2 = __ldg(g_h1 + s2 * 32 + lane);
                float v3 = __ldg(g_h1 + s3 * 32 + lane);
                acc += (v0 + v1) + (v2 + v3);
            }
            for (; j < end; j++)
                acc += __ldg(g_h1 + __ldg(g_csr + j) * 32 + lane);
            float inv = 1.0f / fmaxf((float)(end - beg), 1.0f);
            rows[w][lane]      = acc * inv;
            rows[w][32 + lane] = g_h1[node * 32 + lane];
            __syncwarp();
            float a0 = bb0, a1 = bb32;
#pragma unroll
            for (int k = 0; k < 32; k++) {
                float m = rows[w][k], h = rows[w][32 + k];
                a0 = fmaf(m, swl[k * 64 + lane],      fmaf(h, swr[k * 64 + lane],      a0));
                a1 = fmaf(m, swl[k * 64 + 32 + lane], fmaf(h, swr[k * 64 + 32 + lane], a1));
            }
            uint32_t j0 = (uint32_t)(node * 64 + lane);
            a0 = drop_bit<DK1.a, DK1.b>(j0)       ? 0.f : 2.0f * a0;
            a1 = drop_bit<DK1.a, DK1.b>(j0 + 32u) ? 0.f : 2.0f * a1;
            float ss = a0 * a0 + a1 * a1;
#pragma unroll
            for (int o = 16; o > 0; o >>= 1)
                ss += __shfl_xor_sync(0xffffffffu, ss, o);
            float scale = 1.0f / fmaxf(sqrtf(ss), 1e-12f);
            out[node * 64 + lane]      = a0 * scale;
            out[node * 64 + 32 + lane] = a1 * scale;
            __syncwarp();
        }
    }
}

// ---------------- launch ----------------------------------------------------
extern "C" void kernel_launch(void* const* d_in, const int* in_sizes, int n_in,
                              void* d_out, int out_size) {
    const float*    x   = (const float*)d_in[0];
    const uint32_t* ei  = (const uint32_t*)d_in[1];   // int32 or int64 (detected)
    const float*    W1l = (const float*)d_in[2];
    const float*    b1  = (const float*)d_in[3];
    const float*    W1r = (const float*)d_in[4];
    const float*    W2l = (const float*)d_in[5];
    const float*    b2  = (const float*)d_in[6];
    const float*    W2r = (const float*)d_in[7];
    float* out = (float*)d_out;

    k_reset<<<(N_NODES + NT) / NT + 1, NT>>>(ei);
    k_main<<<NB, NT>>>(x, ei, W1l, b1, W1r, W2l, b2, W2r, out);
}

// round 7
// speedup vs baseline: 1.5692x; 1.5692x over previous
#include <cuda_runtime.h>
#include <cstdint>

#define N_NODES 100000
#define N_EDGES 1600000
#define SCAN_BLK 512
#define NSCAN_BLKS 196   // 196*512 >= N_NODES

// ---------------- scratch (device globals; no allocation allowed) ----------
__device__ float g_y[N_NODES * 32];     // x @ W1_l
__device__ float g_z[N_NODES * 32];     // x @ W1_r
__device__ float g_h1[N_NODES * 32];
__device__ int2  g_edge[N_EDGES];       // packed (src, dst)
__device__ int   g_csr[N_EDGES];        // src ids grouped by dst
__device__ int   g_off[N_NODES + 1];    // counts -> exclusive offsets
__device__ int   g_part[N_NODES];       // scan partials
__device__ int   g_cur[N_NODES];        // bucket cursors
__device__ int   g_bsum[256];
__device__ int   g_is64;

// ---------------- JAX threefry2x32 (partitionable scheme) ------------------
struct TF2 { uint32_t a, b; };

__host__ __device__ constexpr uint32_t rotl32(uint32_t v, int r) {
    return (v << r) | (v >> (32 - r));
}

__host__ __device__ constexpr TF2 threefry(uint32_t k0, uint32_t k1,
                                           uint32_t x0, uint32_t x1) {
    const uint32_t ks0 = k0, ks1 = k1, ks2 = k0 ^ k1 ^ 0x1BD11BDAu;
    const int ra[4] = {13, 15, 26, 6};
    const int rb[4] = {17, 29, 16, 24};
    x0 += ks0; x1 += ks1;
#pragma unroll
    for (int i = 0; i < 4; i++) { x0 += x1; x1 = rotl32(x1, ra[i]); x1 ^= x0; }
    x0 += ks1; x1 += ks2 + 1u;
#pragma unroll
    for (int i = 0; i < 4; i++) { x0 += x1; x1 = rotl32(x1, rb[i]); x1 ^= x0; }
    x0 += ks2; x1 += ks0 + 2u;
#pragma unroll
    for (int i = 0; i < 4; i++) { x0 += x1; x1 = rotl32(x1, ra[i]); x1 ^= x0; }
    x0 += ks0; x1 += ks1 + 3u;
#pragma unroll
    for (int i = 0; i < 4; i++) { x0 += x1; x1 = rotl32(x1, rb[i]); x1 ^= x0; }
    x0 += ks1; x1 += ks2 + 4u;
#pragma unroll
    for (int i = 0; i < 4; i++) { x0 += x1; x1 = rotl32(x1, ra[i]); x1 ^= x0; }
    x0 += ks2; x1 += ks0 + 5u;
    return {x0, x1};
}

constexpr TF2 DK0 = threefry(0u, 42u, 0u, 0u);
constexpr TF2 DK1 = threefry(0u, 42u, 0u, 1u);

template <uint32_t K0, uint32_t K1>
__device__ __forceinline__ bool drop_bit(uint32_t j) {
    TF2 r = threefry(K0, K1, 0u, j);
    return ((r.a ^ r.b) >> 31) != 0;   // MSB set -> u >= 0.5 -> dropped
}

// ---------------- packed f32x2 helpers (sm_103a) ---------------------------
__device__ __forceinline__ unsigned long long pk2(float x, float y) {
    unsigned long long r;
    asm("mov.b64 %0, {%1, %2};" : "=l"(r) : "f"(x), "f"(y));
    return r;
}
__device__ __forceinline__ unsigned long long fma2(unsigned long long a,
                                                   unsigned long long b,
                                                   unsigned long long c) {
    unsigned long long d;
    asm("fma.rn.f32x2 %0, %1, %2, %3;" : "=l"(d) : "l"(a), "l"(b), "l"(c));
    return d;
}
__device__ __forceinline__ void upk2(unsigned long long v, float& x, float& y) {
    asm("mov.b64 {%0, %1}, %2;" : "=f"(x), "=f"(y) : "l"(v));
}

// ---------------- kernels --------------------------------------------------
// fused: y = x @ W1_l, z = x @ W1_r; zero histogram; dtype detect.
// 4 nodes per warp; weights pre-packed float2 in smem; packed FMA.
__global__ void __launch_bounds__(256) k_pre(const float* __restrict__ x,
                      const float* __restrict__ Wl,
                      const float* __restrict__ Wr,
                      const uint32_t* __restrict__ ei) {
    __shared__ float2 swlr[64 * 32];      // (Wl, Wr) pairs, 16KB
    __shared__ float  rows[8][4][64];     // 8KB
    int tid = threadIdx.x;
    for (int i = tid; i < 2048; i += 256) swlr[i] = make_float2(Wl[i], Wr[i]);
    int gt = blockIdx.x * 256 + tid;
    if (gt <= N_NODES) g_off[gt] = 0;
    if (blockIdx.x == 0 && tid == 0) {
        int is64 = 1;
        for (int k = 0; k < 64; k++)
            if (ei[2 * k + 1] != 0u) { is64 = 0; break; }
        g_is64 = is64;
    }
    int w = tid >> 5, lane = tid & 31;
    int nb = blockIdx.x * 32 + w * 4;     // grid = 3125 exact
#pragma unroll
    for (int n = 0; n < 4; n++) {
        rows[w][n][lane]      = x[(nb + n) * 64 + lane];
        rows[w][n][32 + lane] = x[(nb + n) * 64 + 32 + lane];
    }
    __syncthreads();
    unsigned long long acc[4];
#pragma unroll
    for (int n = 0; n < 4; n++) acc[n] = pk2(0.f, 0.f);
#pragma unroll
    for (int k = 0; k < 64; k++) {
        float2 wv = swlr[k * 32 + lane];
        unsigned long long wp = pk2(wv.x, wv.y);
#pragma unroll
        for (int n = 0; n < 4; n++) {
            float xv = rows[w][n][k];
            acc[n] = fma2(pk2(xv, xv), wp, acc[n]);
        }
    }
#pragma unroll
    for (int n = 0; n < 4; n++) {
        float yl, yr;
        upk2(acc[n], yl, yr);
        g_y[(nb + n) * 32 + lane] = yl;
        g_z[(nb + n) * 32 + lane] = yr;
    }
}

// pack edges + dst histogram
__global__ void k_prep(const uint32_t* __restrict__ ei) {
    int e = blockIdx.x * blockDim.x + threadIdx.x;
    if (e >= N_EDGES) return;
    int s, d;
    if (g_is64) {
        uint2 sv = reinterpret_cast<const uint2*>(ei)[e];
        uint2 dv = reinterpret_cast<const uint2*>(ei)[N_EDGES + e];
        s = (int)sv.x; d = (int)dv.x;
    } else {
        s = (int)ei[e];
        d = (int)ei[N_EDGES + e];
    }
    g_edge[e] = make_int2(s, d);
    atomicAdd(&g_off[d], 1);
}

// exclusive scan over 100k counts: 3 tiny kernels
__global__ void k_scan_a() {
    __shared__ int sh[SCAN_BLK];
    int i = blockIdx.x * SCAN_BLK + threadIdx.x;
    int v = (i < N_NODES) ? g_off[i] : 0;
    sh[threadIdx.x] = v;
    __syncthreads();
    for (int o = 1; o < SCAN_BLK; o <<= 1) {
        int t = (threadIdx.x >= o) ? sh[threadIdx.x - o] : 0;
        __syncthreads();
        sh[threadIdx.x] += t;
        __syncthreads();
    }
    if (i < N_NODES) g_part[i] = sh[threadIdx.x] - v;    // exclusive in-block
    if (threadIdx.x == SCAN_BLK - 1) g_bsum[blockIdx.x] = sh[threadIdx.x];
}

__global__ void k_scan_b() {                             // 1 block of 256
    __shared__ int sh[256];
    int v = (threadIdx.x < NSCAN_BLKS) ? g_bsum[threadIdx.x] : 0;
    sh[threadIdx.x] = v;
    __syncthreads();
    for (int o = 1; o < 256; o <<= 1) {
        int t = (threadIdx.x >= o) ? sh[threadIdx.x - o] : 0;
        __syncthreads();
        sh[threadIdx.x] += t;
        __syncthreads();
    }
    if (threadIdx.x < NSCAN_BLKS) g_bsum[threadIdx.x] = sh[threadIdx.x] - v;
}

__global__ void k_scan_c() {
    int i = blockIdx.x * SCAN_BLK + threadIdx.x;
    if (i < N_NODES) {
        int o = g_part[i] + g_bsum[i / SCAN_BLK];
        g_off[i] = o;
        g_cur[i] = o;
    }
    if (i == 0) g_off[N_NODES] = N_EDGES;
}

__global__ void k_bucket() {
    int e = blockIdx.x * blockDim.x + threadIdx.x;
    if (e >= N_EDGES) return;
    int2 p = g_edge[e];
    int pos = atomicAdd(&g_cur[p.y], 1);
    g_csr[pos] = p.x;
}

// layer 1: warp per node; gather-sum y rows over CSR, fuse bias+z+lrelu+dropout
__global__ void k_agg1(const float* __restrict__ b) {
    int w = threadIdx.x >> 5, lane = threadIdx.x & 31;
    int node = blockIdx.x * 8 + w;                    // grid = 12500 exact
    int beg = g_off[node], end = g_off[node + 1];
    float acc = 0.f;
    int j = beg;
    for (; j + 4 <= end; j += 4) {
        int s0 = __ldg(g_csr + j),     s1 = __ldg(g_csr + j + 1);
        int s2 = __ldg(g_csr + j + 2), s3 = __ldg(g_csr + j + 3);
        float v0 = __ldg(g_y + s0 * 32 + lane);
        float v1 = __ldg(g_y + s1 * 32 + lane);
        float v2 = __ldg(g_y + s2 * 32 + lane);
        float v3 = __ldg(g_y + s3 * 32 + lane);
        acc += (v0 + v1) + (v2 + v3);
    }
    for (; j < end; j++)
        acc += __ldg(g_y + __ldg(g_csr + j) * 32 + lane);
    float inv = 1.0f / fmaxf((float)(end - beg), 1.0f);
    float v = fmaf(acc, inv, b[lane] + g_z[node * 32 + lane]);
    v = v > 0.f ? v : 0.01f * v;
    uint32_t jj = (uint32_t)(node * 32 + lane);
    g_h1[jj] = drop_bit<DK0.a, DK0.b>(jj) ? 0.f : 2.0f * v;
}

// layer 2 fused: gather-mean, per-node GEMMs (4 nodes/warp, packed weights),
// dropout, l2norm
__global__ void __launch_bounds__(256) k_agg2(const float* __restrict__ Wl,
                       const float* __restrict__ b,
                       const float* __restrict__ Wr,
                       float* __restrict__ out) {
    __shared__ float2 swl2[32 * 32], swr2[32 * 32];   // 8KB + 8KB
    __shared__ float  rows[8][4][64];                 // 8KB
    int tid = threadIdx.x;
    for (int i = tid; i < 1024; i += 256) {
        int k = i >> 5, c = i & 31;
        swl2[i] = make_float2(Wl[k * 64 + c], Wl[k * 64 + 32 + c]);
        swr2[i] = make_float2(Wr[k * 64 + c], Wr[k * 64 + 32 + c]);
    }
    __syncthreads();
    int w = tid >> 5, lane = tid & 31;
    int nb = blockIdx.x * 32 + w * 4;                 // grid = 3125 exact
#pragma unroll
    for (int n = 0; n < 4; n++) {
        int node = nb + n;
        int beg = g_off[node], end = g_off[node + 1];
        float acc = 0.f;
        int j = beg;
        for (; j + 4 <= end; j += 4) {
            int s0 = __ldg(g_csr + j),     s1 = __ldg(g_csr + j + 1);
            int s2 = __ldg(g_csr + j + 2), s3 = __ldg(g_csr + j + 3);
            float v0 = __ldg(g_h1 + s0 * 32 + lane);
            float v1 = __ldg(g_h1 + s1 * 32 + lane);
            float v2 = __ldg(g_h1 + s2 * 32 + lane);
            float v3 = __ldg(g_h1 + s3 * 32 + lane);
            acc += (v0 + v1) + (v2 + v3);
        }
        for (; j < end; j++)
            acc += __ldg(g_h1 + __ldg(g_csr + j) * 32 + lane);
        float inv = 1.0f / fmaxf((float)(end - beg), 1.0f);
        rows[w][n][lane]      = acc * inv;
        rows[w][n][32 + lane] = g_h1[node * 32 + lane];
    }
    __syncwarp();
    float bb0 = b[lane], bb1 = b[32 + lane];
    float a0[4], a1[4];
#pragma unroll
    for (int n = 0; n < 4; n++) { a0[n] = bb0; a1[n] = bb1; }
#pragma unroll
    for (int k = 0; k < 32; k++) {
        float2 wl = swl2[k * 32 + lane];
        float2 wr = swr2[k * 32 + lane];
#pragma unroll
        for (int n = 0; n < 4; n++) {
            float m = rows[w][n][k];
            float h = rows[w][n][32 + k];
            a0[n] = fmaf(m, wl.x, fmaf(h, wr.x, a0[n]));
            a1[n] = fmaf(m, wl.y, fmaf(h, wr.y, a1[n]));
        }
    }
#pragma unroll
    for (int n = 0; n < 4; n++) {
        int node = nb + n;
        uint32_t j0 = (uint32_t)(node * 64 + lane);
        float v0 = drop_bit<DK1.a, DK1.b>(j0)       ? 0.f : 2.0f * a0[n];
        float v1 = drop_bit<DK1.a, DK1.b>(j0 + 32u) ? 0.f : 2.0f * a1[n];
        float ss = v0 * v0 + v1 * v1;
#pragma unroll
        for (int o = 16; o > 0; o >>= 1)
            ss += __shfl_xor_sync(0xffffffffu, ss, o);
        float scale = 1.0f / fmaxf(sqrtf(ss), 1e-12f);
        out[node * 64 + lane]      = v0 * scale;
        out[node * 64 + 32 + lane] = v1 * scale;
    }
}

// ---------------- launch ----------------------------------------------------
extern "C" void kernel_launch(void* const* d_in, const int* in_sizes, int n_in,
                              void* d_out, int out_size) {
    const float*    x   = (const float*)d_in[0];
    const uint32_t* ei  = (const uint32_t*)d_in[1];   // int32 or int64 (detected)
    const float*    W1l = (const float*)d_in[2];
    const float*    b1  = (const float*)d_in[3];
    const float*    W1r = (const float*)d_in[4];
    const float*    W2l = (const float*)d_in[5];
    const float*    b2  = (const float*)d_in[6];
    const float*    W2r = (const float*)d_in[7];
    float* out = (float*)d_out;

    k_pre<<<N_NODES / 32, 256>>>(x, W1l, W1r, ei);     // 3125 blocks
    k_prep<<<(N_EDGES + 255) / 256, 256>>>(ei);        // 6250 blocks
    k_scan_a<<<NSCAN_BLKS, SCAN_BLK>>>();
    k_scan_b<<<1, 256>>>();
    k_scan_c<<<NSCAN_BLKS, SCAN_BLK>>>();
    k_bucket<<<(N_EDGES + 255) / 256, 256>>>();        // 6250 blocks
    k_agg1<<<N_NODES / 8, 256>>>(b1);                  // 12500 blocks
    k_agg2<<<N_NODES / 32, 256>>>(W2l, b2, W2r, out);  // 3125 blocks
}